// round 1
// baseline (speedup 1.0000x reference)
#include <cuda_runtime.h>
#include <cuda_bf16.h>

// Problem dims (fixed)
#define B_  16
#define Q_  256
#define K_  256
#define H_  256
#define DV_ 256

// Scratch (device globals; no allocation allowed)
__device__ float g_qp[B_ * Q_ * H_];       // projected queries
__device__ float g_kp[B_ * K_ * H_];       // projected keys
__device__ float g_scores[B_ * Q_ * K_];   // pre-softmax scores

__device__ __forceinline__ float tanh_fast(float x) {
    float y;
    asm("tanh.approx.f32 %0, %1;" : "=f"(y) : "f"(x));
    return y;
}

// ---------------------------------------------------------------------------
// Kernel 1: projection GEMM  C[M,256] = A[M,256] * W[256,256]^T
// BM=64, BN=64, BK=32, 256 threads, 4x4 register tile.
// sel==0 -> write g_qp, sel==1 -> write g_kp
// ---------------------------------------------------------------------------
__global__ __launch_bounds__(256) void proj_gemm(const float* __restrict__ A,
                                                 const float* __restrict__ W,
                                                 int sel) {
    constexpr int BM = 64, BN = 64, BK = 32;
    __shared__ float As[BK][BM + 4];  // [k][m], padded stride 68
    __shared__ float Bs[BK][BN + 4];

    float* __restrict__ C = sel ? g_kp : g_qp;

    const int tid = threadIdx.x;
    const int m0 = blockIdx.y * BM;
    const int n0 = blockIdx.x * BN;
    const int ty = tid >> 4;       // 0..15
    const int tx = tid & 15;       // 0..15

    float acc[4][4];
#pragma unroll
    for (int i = 0; i < 4; i++)
#pragma unroll
        for (int j = 0; j < 4; j++) acc[i][j] = 0.0f;

    const int lr = tid >> 3;        // 0..31
    const int lc = (tid & 7) * 4;   // 0,4,...,28

    for (int kt = 0; kt < H_; kt += BK) {
        // Load A tile (64 x 32) and W tile (64 x 32), transpose into smem
        float4 a0 = *(const float4*)&A[(m0 + lr) * H_ + kt + lc];
        float4 a1 = *(const float4*)&A[(m0 + lr + 32) * H_ + kt + lc];
        float4 b0 = *(const float4*)&W[(n0 + lr) * H_ + kt + lc];
        float4 b1 = *(const float4*)&W[(n0 + lr + 32) * H_ + kt + lc];

        As[lc + 0][lr] = a0.x; As[lc + 1][lr] = a0.y;
        As[lc + 2][lr] = a0.z; As[lc + 3][lr] = a0.w;
        As[lc + 0][lr + 32] = a1.x; As[lc + 1][lr + 32] = a1.y;
        As[lc + 2][lr + 32] = a1.z; As[lc + 3][lr + 32] = a1.w;
        Bs[lc + 0][lr] = b0.x; Bs[lc + 1][lr] = b0.y;
        Bs[lc + 2][lr] = b0.z; Bs[lc + 3][lr] = b0.w;
        Bs[lc + 0][lr + 32] = b1.x; Bs[lc + 1][lr + 32] = b1.y;
        Bs[lc + 2][lr + 32] = b1.z; Bs[lc + 3][lr + 32] = b1.w;

        __syncthreads();

#pragma unroll
        for (int kk = 0; kk < BK; kk++) {
            float a[4], b[4];
#pragma unroll
            for (int i = 0; i < 4; i++) a[i] = As[kk][ty * 4 + i];
#pragma unroll
            for (int j = 0; j < 4; j++) b[j] = Bs[kk][tx * 4 + j];
#pragma unroll
            for (int i = 0; i < 4; i++)
#pragma unroll
                for (int j = 0; j < 4; j++) acc[i][j] += a[i] * b[j];
        }
        __syncthreads();
    }

#pragma unroll
    for (int i = 0; i < 4; i++) {
        float4 v;
        v.x = acc[i][0]; v.y = acc[i][1]; v.z = acc[i][2]; v.w = acc[i][3];
        *(float4*)&C[(m0 + ty * 4 + i) * H_ + n0 + tx * 4] = v;
    }
}

// ---------------------------------------------------------------------------
// Kernel 2: scores[b,q,k] = sum_h w_v[h] * tanh(qp[b,q,h] + kp[b,k,h])
// Block: 32x32 (q,k) tile, 256 threads, 2x2 per thread. MUFU.TANH bound.
// ---------------------------------------------------------------------------
__global__ __launch_bounds__(256) void scores_kernel(const float* __restrict__ wv) {
    const int b = blockIdx.z;
    const int q0 = blockIdx.y * 32;
    const int k0 = blockIdx.x * 32;

    __shared__ float qs[32][33];
    __shared__ float ks[32][33];
    __shared__ float ws[H_];

    const int tid = threadIdx.x;
    ws[tid] = wv[tid];

    const int ty = tid >> 4;      // 0..15
    const int tx = tid & 15;      // 0..15

    const float* qbase = g_qp + (b * Q_ + q0) * H_;
    const float* kbase = g_kp + (b * K_ + k0) * H_;

    float a00 = 0.f, a01 = 0.f, a10 = 0.f, a11 = 0.f;

    const int lr = tid >> 5;   // 0..7
    const int lc = tid & 31;   // 0..31

    for (int hc = 0; hc < H_; hc += 32) {
        __syncthreads();
#pragma unroll
        for (int rr = 0; rr < 4; rr++) {
            int row = lr + rr * 8;
            qs[row][lc] = qbase[row * H_ + hc + lc];
            ks[row][lc] = kbase[row * H_ + hc + lc];
        }
        __syncthreads();

#pragma unroll
        for (int hh = 0; hh < 32; hh++) {
            float w = ws[hc + hh];
            float qv0 = qs[ty * 2 + 0][hh];
            float qv1 = qs[ty * 2 + 1][hh];
            float kv0 = ks[tx * 2 + 0][hh];
            float kv1 = ks[tx * 2 + 1][hh];
            a00 += w * tanh_fast(qv0 + kv0);
            a01 += w * tanh_fast(qv0 + kv1);
            a10 += w * tanh_fast(qv1 + kv0);
            a11 += w * tanh_fast(qv1 + kv1);
        }
    }

    float* sbase = g_scores + (b * Q_ + q0) * K_ + k0;
    sbase[(ty * 2 + 0) * K_ + tx * 2 + 0] = a00;
    sbase[(ty * 2 + 0) * K_ + tx * 2 + 1] = a01;
    sbase[(ty * 2 + 1) * K_ + tx * 2 + 0] = a10;
    sbase[(ty * 2 + 1) * K_ + tx * 2 + 1] = a11;
}

// ---------------------------------------------------------------------------
// Kernel 3: fused row-softmax + out = attn @ values
// Block handles 8 q-rows for one batch. 256 threads.
// ---------------------------------------------------------------------------
__global__ __launch_bounds__(256) void softmax_av(const float* __restrict__ V,
                                                  float* __restrict__ out) {
    const int b = blockIdx.y;
    const int q0 = blockIdx.x * 8;

    __shared__ float sattn[8][256];

    const int tid = threadIdx.x;
    const int w = tid >> 5;      // warp -> row 0..7
    const int lane = tid & 31;

    // --- softmax of row (q0 + w) ---
    const float* srow = g_scores + (b * Q_ + q0 + w) * K_;
    float vals[8];
    float mx = -1e30f;
#pragma unroll
    for (int i = 0; i < 8; i++) {
        vals[i] = srow[lane + i * 32];
        mx = fmaxf(mx, vals[i]);
    }
#pragma unroll
    for (int off = 16; off; off >>= 1)
        mx = fmaxf(mx, __shfl_xor_sync(0xffffffffu, mx, off));
    float sum = 0.f;
#pragma unroll
    for (int i = 0; i < 8; i++) {
        vals[i] = __expf(vals[i] - mx);
        sum += vals[i];
    }
#pragma unroll
    for (int off = 16; off; off >>= 1)
        sum += __shfl_xor_sync(0xffffffffu, sum, off);
    float inv = 1.0f / sum;
#pragma unroll
    for (int i = 0; i < 8; i++) sattn[w][lane + i * 32] = vals[i] * inv;

    __syncthreads();

    // --- AV: each thread owns one output column c for all 8 rows ---
    const float* vb = V + b * K_ * DV_;
    const int c = tid;
    float acc[8];
#pragma unroll
    for (int r = 0; r < 8; r++) acc[r] = 0.f;

    for (int k4 = 0; k4 < K_ / 4; k4++) {
        int k = k4 * 4;
        float v0 = vb[(k + 0) * DV_ + c];
        float v1 = vb[(k + 1) * DV_ + c];
        float v2 = vb[(k + 2) * DV_ + c];
        float v3 = vb[(k + 3) * DV_ + c];
#pragma unroll
        for (int r = 0; r < 8; r++) {
            float4 p = *(const float4*)&sattn[r][k];
            acc[r] += p.x * v0 + p.y * v1 + p.z * v2 + p.w * v3;
        }
    }

#pragma unroll
    for (int r = 0; r < 8; r++)
        out[(b * Q_ + q0 + r) * DV_ + c] = acc[r];
}

// ---------------------------------------------------------------------------
extern "C" void kernel_launch(void* const* d_in, const int* in_sizes, int n_in,
                              void* d_out, int out_size) {
    const float* queries = (const float*)d_in[0];  // [B,Q,H]
    const float* keys    = (const float*)d_in[1];  // [B,K,H]
    const float* values  = (const float*)d_in[2];  // [B,K,DV]
    const float* W_q     = (const float*)d_in[3];  // [H,H]
    const float* W_k     = (const float*)d_in[4];  // [H,H]
    const float* w_v     = (const float*)d_in[5];  // [H]
    float* out = (float*)d_out;

    // projections: M = B*Q = 4096 rows, N = 256
    dim3 gproj(H_ / 64, (B_ * Q_) / 64);
    proj_gemm<<<gproj, 256>>>(queries, W_q, 0);
    proj_gemm<<<gproj, 256>>>(keys,    W_k, 1);

    dim3 gscores(K_ / 32, Q_ / 32, B_);
    scores_kernel<<<gscores, 256>>>(w_v);

    dim3 gav(Q_ / 8, B_);
    softmax_av<<<gav, 256>>>(values, out);
}